// round 2
// baseline (speedup 1.0000x reference)
#include <cuda_runtime.h>
#include <math.h>

// Problem constants (from reference): B=1048576, M=8, K=3, R=8
#define M 8
#define Kc 3
#define R 8

__global__ __launch_bounds__(256, 8)
void anfis_kernel(const float* __restrict__ x,
                  const float* __restrict__ c,
                  const float* __restrict__ log_sigma,
                  const float* __restrict__ cons,      // (R, M+1)
                  const int*   __restrict__ rules,     // (R, M)
                  float* __restrict__ out, int B)
{
    __shared__ float s_c[M * Kc];     // centers
    __shared__ float s_h[M * Kc];     // 0.5 / sigma^2
    __shared__ float s_cons[R * (M + 1)];
    __shared__ int   s_rules[R * M];

    const int tid = threadIdx.x;
    if (tid < M * Kc) {
        s_c[tid] = c[tid];
        float sg = expf(log_sigma[tid]) + 1e-6f;
        s_h[tid] = 0.5f / (sg * sg);
    }
    if (tid < R * (M + 1)) s_cons[tid]  = cons[tid];
    if (tid < R * M)       s_rules[tid] = rules[tid];
    __syncthreads();

    const int b = blockIdx.x * blockDim.x + tid;
    if (b >= B) return;

    // ---- load x row: 32 contiguous bytes, two float4 ----
    const float4 xa = *(const float4*)(x + (size_t)b * M);
    const float4 xb = *(const float4*)(x + (size_t)b * M + 4);
    float xv[M] = {xa.x, xa.y, xa.z, xa.w, xb.x, xb.y, xb.z, xb.w};

    // ---- quadratic terms q[m][k] = 0.5*((x-c)/sigma)^2 (all static indices -> regs) ----
    float q[M][Kc];
    #pragma unroll
    for (int m = 0; m < M; m++) {
        #pragma unroll
        for (int k = 0; k < Kc; k++) {
            float d = xv[m] - s_c[m * Kc + k];
            q[m][k] = d * d * s_h[m * Kc + k];
        }
    }

    // ---- rule consequents: y_r[r] = cons[r][0] + x . cons[r][1:] ----
    float yr[R];
    #pragma unroll
    for (int r = 0; r < R; r++) {
        float acc = s_cons[r * (M + 1)];
        #pragma unroll
        for (int m = 0; m < M; m++)
            acc = fmaf(xv[m], s_cons[r * (M + 1) + 1 + m], acc);
        yr[r] = acc;
    }

    // ---- firing strengths: exp(-sum of selected q) ; only 8 __expf per row ----
    float f[R];
    float fsum = 0.f;
    #pragma unroll
    for (int r = 0; r < R; r++) {
        float s = 0.f;
        #pragma unroll
        for (int m = 0; m < M; m++) {
            int k = s_rules[r * M + m];
            float v = (k == 0) ? q[m][0] : ((k == 1) ? q[m][1] : q[m][2]);
            s += v;
        }
        f[r] = __expf(-s);
        fsum += f[r];
    }

    const float inv = 1.0f / (fsum + 1e-8f);

    float wn[R];
    float y = 0.f;
    #pragma unroll
    for (int r = 0; r < R; r++) {
        wn[r] = f[r] * inv;
        y = fmaf(wn[r], yr[r], y);
    }

    // ---- outputs: flat concat  y[0,B) | w_norm[B,9B) | y_r[9B,17B) ----
    out[b] = y;

    float4* wo = (float4*)(out + (size_t)B + (size_t)b * R);
    wo[0] = make_float4(wn[0], wn[1], wn[2], wn[3]);
    wo[1] = make_float4(wn[4], wn[5], wn[6], wn[7]);

    float4* yo = (float4*)(out + (size_t)B * 9 + (size_t)b * R);
    yo[0] = make_float4(yr[0], yr[1], yr[2], yr[3]);
    yo[1] = make_float4(yr[4], yr[5], yr[6], yr[7]);
}

extern "C" void kernel_launch(void* const* d_in, const int* in_sizes, int n_in,
                              void* d_out, int out_size)
{
    const float* x         = (const float*)d_in[0];
    const float* c         = (const float*)d_in[1];
    const float* log_sigma = (const float*)d_in[2];
    const float* cons      = (const float*)d_in[3];
    const int*   rules     = (const int*)d_in[4];
    float* out = (float*)d_out;

    const int B = in_sizes[0] / M;   // 1048576
    const int threads = 256;
    const int blocks = (B + threads - 1) / threads;
    anfis_kernel<<<blocks, threads>>>(x, c, log_sigma, cons, rules, out, B);
}

// round 3
// speedup vs baseline: 1.2152x; 1.2152x over previous
#include <cuda_runtime.h>
#include <math.h>

// Problem constants: B=1048576, M=8, K=3, R=8
#define M 8
#define Kc 3
#define R 8
#define CW 28   // padded coefficient row width (floats) per rule: 28*4=112B, 16B aligned

__global__ __launch_bounds__(256, 4)
void anfis_kernel(const float* __restrict__ x,
                  const float* __restrict__ c,
                  const float* __restrict__ log_sigma,
                  const float* __restrict__ cons,      // (R, M+1)
                  const int*   __restrict__ rules,     // (R, M)
                  float* __restrict__ out, int B)
{
    // Per-rule packed coefficients:
    //  [0..7]  a_m  = -h            (coef of x_m^2 in firing exponent)
    //  [8..15] b_m  = 2*h*c         (coef of x_m)
    //  [16]    k0   = -sum h*c^2    (constant term)
    //  [17]    bias = cons[r][0]
    //  [18..25] w_m = cons[r][1+m]
    //  [26..27] pad
    __shared__ float s_coef[R * CW];

    const int tid = threadIdx.x;

    // ---- in-block setup: 8 threads, one rule each ----
    if (tid < R) {
        const int r = tid;
        float k0 = 0.f;
        #pragma unroll
        for (int m = 0; m < M; m++) {
            int k = rules[r * M + m];
            float sg = expf(log_sigma[m * Kc + k]) + 1e-6f;
            float h  = 0.5f / (sg * sg);
            float cc = c[m * Kc + k];
            s_coef[r * CW + m]     = -h;
            s_coef[r * CW + 8 + m] = 2.f * h * cc;
            k0 -= h * cc * cc;
            s_coef[r * CW + 18 + m] = cons[r * (M + 1) + 1 + m];
        }
        s_coef[r * CW + 16] = k0;
        s_coef[r * CW + 17] = cons[r * (M + 1)];
        s_coef[r * CW + 26] = 0.f;
        s_coef[r * CW + 27] = 0.f;
    }
    __syncthreads();

    const int b = blockIdx.x * blockDim.x + tid;
    if (b >= B) return;

    // ---- load x row: 32 contiguous bytes ----
    const float4 xa = *(const float4*)(x + (size_t)b * M);
    const float4 xb = *(const float4*)(x + (size_t)b * M + 4);
    const float xv[M]  = {xa.x, xa.y, xa.z, xa.w, xb.x, xb.y, xb.z, xb.w};
    float x2[M];
    #pragma unroll
    for (int m = 0; m < M; m++) x2[m] = xv[m] * xv[m];

    const float4* S4 = (const float4*)s_coef;   // 7 float4 per rule

    float f[R], yr[R];
    float fsum = 0.f;
    #pragma unroll
    for (int r = 0; r < R; r++) {
        const float4 A0 = S4[r * 7 + 0];
        const float4 A1 = S4[r * 7 + 1];
        const float4 B0 = S4[r * 7 + 2];
        const float4 B1 = S4[r * 7 + 3];
        const float4 C0 = S4[r * 7 + 4];
        const float4 C1 = S4[r * 7 + 5];
        const float4 C2 = S4[r * 7 + 6];

        // firing exponent (two independent accumulators for ILP)
        float e0 = C0.x;                       // k0
        e0 = fmaf(A0.x, x2[0], e0);
        e0 = fmaf(A0.y, x2[1], e0);
        e0 = fmaf(A0.z, x2[2], e0);
        e0 = fmaf(A0.w, x2[3], e0);
        e0 = fmaf(A1.x, x2[4], e0);
        e0 = fmaf(A1.y, x2[5], e0);
        e0 = fmaf(A1.z, x2[6], e0);
        e0 = fmaf(A1.w, x2[7], e0);
        float e1 = 0.f;
        e1 = fmaf(B0.x, xv[0], e1);
        e1 = fmaf(B0.y, xv[1], e1);
        e1 = fmaf(B0.z, xv[2], e1);
        e1 = fmaf(B0.w, xv[3], e1);
        e1 = fmaf(B1.x, xv[4], e1);
        e1 = fmaf(B1.y, xv[5], e1);
        e1 = fmaf(B1.z, xv[6], e1);
        e1 = fmaf(B1.w, xv[7], e1);
        f[r] = __expf(e0 + e1);
        fsum += f[r];

        // consequent: bias + x . w
        float t = fmaf(C0.z, xv[0], C0.y);
        t = fmaf(C0.w, xv[1], t);
        t = fmaf(C1.x, xv[2], t);
        t = fmaf(C1.y, xv[3], t);
        t = fmaf(C1.z, xv[4], t);
        t = fmaf(C1.w, xv[5], t);
        t = fmaf(C2.x, xv[6], t);
        t = fmaf(C2.y, xv[7], t);
        yr[r] = t;
    }

    const float inv = __fdividef(1.0f, fsum + 1e-8f);

    float wn[R];
    float y = 0.f;
    #pragma unroll
    for (int r = 0; r < R; r++) {
        wn[r] = f[r] * inv;
        y = fmaf(wn[r], yr[r], y);
    }

    // ---- outputs: flat concat  y[0,B) | w_norm[B,9B) | y_r[9B,17B) ----
    out[b] = y;

    float4* wo = (float4*)(out + (size_t)B + (size_t)b * R);
    wo[0] = make_float4(wn[0], wn[1], wn[2], wn[3]);
    wo[1] = make_float4(wn[4], wn[5], wn[6], wn[7]);

    float4* yo = (float4*)(out + (size_t)B * 9 + (size_t)b * R);
    yo[0] = make_float4(yr[0], yr[1], yr[2], yr[3]);
    yo[1] = make_float4(yr[4], yr[5], yr[6], yr[7]);
}

extern "C" void kernel_launch(void* const* d_in, const int* in_sizes, int n_in,
                              void* d_out, int out_size)
{
    const float* x         = (const float*)d_in[0];
    const float* c         = (const float*)d_in[1];
    const float* log_sigma = (const float*)d_in[2];
    const float* cons      = (const float*)d_in[3];
    const int*   rules     = (const int*)d_in[4];
    float* out = (float*)d_out;

    const int B = in_sizes[0] / M;   // 1048576
    const int threads = 256;
    const int blocks = (B + threads - 1) / threads;
    anfis_kernel<<<blocks, threads>>>(x, c, log_sigma, cons, rules, out, B);
}